// round 3
// baseline (speedup 1.0000x reference)
#include <cuda_runtime.h>

#define Bq 16
#define Sq 2048
#define Dq 128
#define Hq 8
#define BH (Bq*Hq)
#define CHUNK 32
#define CUT 1e-12f
#define SMEM_FLOATS 45600

// scratch (allocation-free rule: device globals)
__device__ float g_c[BH * Sq];
__device__ float g_P[BH];
__device__ int   g_t0[BH];

// ---------------------------------------------------------------------------
// Kernel A: f = sigmoid(x @ Wf + bf), suffix products, c_t = w_t * sp_t,
// per-(b,h) active start index t0, total product P.
// One block per (b,h). 256 threads.
// ---------------------------------------------------------------------------
__global__ __launch_bounds__(256) void scan_kernel(
    const float* __restrict__ x, const float* __restrict__ router,
    const int* __restrict__ memid, const float* __restrict__ Wf,
    const float* __restrict__ bf, int nm)
{
    __shared__ float f_s[Sq];
    __shared__ float scanbuf[256];
    __shared__ int t0_sh;

    int tid = threadIdx.x;
    int bh = blockIdx.x;
    int b = bh >> 3, h = bh & 7;
    if (tid == 0) t0_sh = Sq;

    int lane = tid & 31, warp = tid >> 5;
    // Wf column for this head, 4 elems per lane
    float wf0 = Wf[(lane * 4 + 0) * Hq + h];
    float wf1 = Wf[(lane * 4 + 1) * Hq + h];
    float wf2 = Wf[(lane * 4 + 2) * Hq + h];
    float wf3 = Wf[(lane * 4 + 3) * Hq + h];
    float bfh = bf[h];

    for (int t = warp; t < Sq; t += 8) {
        float4 xv = *reinterpret_cast<const float4*>(
            &x[((size_t)b * Sq + t) * Dq + lane * 4]);
        float p = xv.x * wf0 + xv.y * wf1 + xv.z * wf2 + xv.w * wf3;
        #pragma unroll
        for (int off = 16; off; off >>= 1)
            p += __shfl_xor_sync(0xffffffffu, p, off);
        if (lane == 0)
            f_s[t] = 1.0f / (1.0f + __expf(-(p + bfh)));
    }
    __syncthreads();

    // per-thread chunk of 8 products
    float p = 1.0f;
    #pragma unroll
    for (int j = 0; j < 8; j++) p *= f_s[tid * 8 + j];
    scanbuf[tid] = p;
    __syncthreads();

    // inclusive suffix-product scan over the 256 chunk products
    for (int off = 1; off < 256; off <<= 1) {
        float v = (tid + off < 256) ? scanbuf[tid + off] : 1.0f;
        __syncthreads();
        scanbuf[tid] *= v;
        __syncthreads();
    }
    if (tid == 0) g_P[bh] = scanbuf[0];   // product of all f

    float running = (tid < 255) ? scanbuf[tid + 1] : 1.0f;  // suffix excl. my chunk
    int mid = *memid;
    int myt0 = Sq;
    #pragma unroll
    for (int j = 7; j >= 0; --j) {
        int t = tid * 8 + j;
        float sp = running;                       // prod_{t' > t} f
        float w = router[((size_t)b * Sq + t) * nm + mid];
        g_c[bh * Sq + t] = w * sp;
        if (sp >= CUT) myt0 = t;                  // sp monotone nondecreasing in t
        running *= f_s[t];
    }
    if (myt0 < Sq) atomicMin(&t0_sh, myt0);
    __syncthreads();
    if (tid == 0) g_t0[bh] = t0_sh & ~(CHUNK - 1);   // chunk-aligned start
}

// ---------------------------------------------------------------------------
// Kernel B: per (b,h):
//   M_out = P*M0 + sum_{t>=t0} c_t * (x_t Wk_h + bk_h)(x_t Wv_h + bv_h)^T
// 256 threads; each owns an 8x8 register tile of M. Chunked rank-32 updates:
//   stage x chunk (transposed) -> project K/V chunk (split warps) -> outer prod.
// ---------------------------------------------------------------------------
__global__ __launch_bounds__(256) void mem_kernel(
    const float* __restrict__ x, const float* __restrict__ M0,
    const float* __restrict__ Wk, const float* __restrict__ bk,
    const float* __restrict__ Wv, const float* __restrict__ bv,
    float* __restrict__ out)
{
    extern __shared__ float sm[];
    float* Wk_s = sm;                 // 128*128
    float* Wv_s = sm + 16384;         // 128*128
    float* xT   = sm + 32768;         // 128 rows * stride 36 (transposed x chunk)
    float* k_s  = sm + 37376;         // 32*128  (rows pre-scaled by c_t)
    float* v_s  = sm + 41472;         // 32*128
    float* c_s  = sm + 45568;         // 32

    int tid = threadIdx.x;
    int bh = blockIdx.x;
    int b = bh >> 3, h = bh & 7;

    // cache this head's Wk / Wv column blocks in smem
    for (int idx = tid; idx < Dq * 32; idx += 256) {
        int d = idx >> 5, q = idx & 31;
        *reinterpret_cast<float4*>(&Wk_s[d * Dq + q * 4]) =
            *reinterpret_cast<const float4*>(&Wk[(size_t)d * (Dq * Hq) + h * Dq + q * 4]);
        *reinterpret_cast<float4*>(&Wv_s[d * Dq + q * 4]) =
            *reinterpret_cast<const float4*>(&Wv[(size_t)d * (Dq * Hq) + h * Dq + q * 4]);
    }

    // M accumulator: thread owns rows d0..d0+7, cols e0..e0+7
    int dg = tid >> 4, eg = tid & 15;
    int d0 = dg * 8, e0 = eg * 8;
    float acc[8][8];
    float P = g_P[bh];
    #pragma unroll
    for (int r = 0; r < 8; r++) {
        float4 m0 = *reinterpret_cast<const float4*>(
            &M0[(((size_t)bh * Dq) + d0 + r) * Dq + e0]);
        float4 m1 = *reinterpret_cast<const float4*>(
            &M0[(((size_t)bh * Dq) + d0 + r) * Dq + e0 + 4]);
        acc[r][0] = P * m0.x; acc[r][1] = P * m0.y;
        acc[r][2] = P * m0.z; acc[r][3] = P * m0.w;
        acc[r][4] = P * m1.x; acc[r][5] = P * m1.y;
        acc[r][6] = P * m1.z; acc[r][7] = P * m1.w;
    }

    // projection mapping: lower 128 threads -> K, upper 128 -> V
    // each computes a 4-row x 8-col tile of the (32 x 128) chunk matrix
    int half = tid >> 7;
    int id2 = tid & 127;
    int rg = id2 & 7;        // rows rg*4 .. rg*4+3
    int cg = id2 >> 3;       // cols cg*8 .. cg*8+7
    const float* Ws = half ? Wv_s : Wk_s;
    float* op = half ? v_s : k_s;
    float bias[8];
    {
        const float* bsrc = half ? bv : bk;
        #pragma unroll
        for (int j = 0; j < 8; j++) bias[j] = bsrc[h * Dq + cg * 8 + j];
    }

    int t0 = g_t0[bh];
    for (int tc = t0; tc < Sq; tc += CHUNK) {
        __syncthreads();
        // stage x chunk transposed: xT[d][i] = x[b, tc+i, d]
        {
            int i = tid & 31, ds = (tid >> 5) << 4;
            int t = tc + i;
            #pragma unroll
            for (int q = 0; q < 4; q++) {
                float4 xv = *reinterpret_cast<const float4*>(
                    &x[((size_t)b * Sq + t) * Dq + ds + q * 4]);
                xT[(ds + q * 4 + 0) * 36 + i] = xv.x;
                xT[(ds + q * 4 + 1) * 36 + i] = xv.y;
                xT[(ds + q * 4 + 2) * 36 + i] = xv.z;
                xT[(ds + q * 4 + 3) * 36 + i] = xv.w;
            }
            if (tid < CHUNK)
                c_s[tid] = g_c[bh * Sq + tc + tid];
        }
        __syncthreads();

        // projection: this thread's K-or-V chunk tile
        float pa[4][8];
        #pragma unroll
        for (int r = 0; r < 4; r++)
            #pragma unroll
            for (int j = 0; j < 8; j++) pa[r][j] = 0.f;

        #pragma unroll 4
        for (int d = 0; d < Dq; d++) {
            float4 xa = *reinterpret_cast<const float4*>(&xT[d * 36 + rg * 4]);
            float4 w0 = *reinterpret_cast<const float4*>(&Ws[d * Dq + cg * 8]);
            float4 w1 = *reinterpret_cast<const float4*>(&Ws[d * Dq + cg * 8 + 4]);
            float xr[4] = {xa.x, xa.y, xa.z, xa.w};
            float wv[8] = {w0.x, w0.y, w0.z, w0.w, w1.x, w1.y, w1.z, w1.w};
            #pragma unroll
            for (int r = 0; r < 4; r++)
                #pragma unroll
                for (int j = 0; j < 8; j++)
                    pa[r][j] += xr[r] * wv[j];
        }
        #pragma unroll
        for (int r = 0; r < 4; r++) {
            int row = rg * 4 + r;
            float scale = half ? 1.0f : c_s[row];   // fold c_t into k rows
            float o[8];
            #pragma unroll
            for (int j = 0; j < 8; j++) o[j] = (pa[r][j] + bias[j]) * scale;
            *reinterpret_cast<float4*>(&op[row * Dq + cg * 8]) =
                make_float4(o[0], o[1], o[2], o[3]);
            *reinterpret_cast<float4*>(&op[row * Dq + cg * 8 + 4]) =
                make_float4(o[4], o[5], o[6], o[7]);
        }
        __syncthreads();

        // rank-32 outer-product update of the 8x8 tile
        #pragma unroll 2
        for (int i = 0; i < CHUNK; i++) {
            float4 k0 = *reinterpret_cast<const float4*>(&k_s[i * Dq + d0]);
            float4 k1 = *reinterpret_cast<const float4*>(&k_s[i * Dq + d0 + 4]);
            float4 v0 = *reinterpret_cast<const float4*>(&v_s[i * Dq + e0]);
            float4 v1 = *reinterpret_cast<const float4*>(&v_s[i * Dq + e0 + 4]);
            float kk[8] = {k0.x, k0.y, k0.z, k0.w, k1.x, k1.y, k1.z, k1.w};
            float vv[8] = {v0.x, v0.y, v0.z, v0.w, v1.x, v1.y, v1.z, v1.w};
            #pragma unroll
            for (int r = 0; r < 8; r++)
                #pragma unroll
                for (int q = 0; q < 8; q++)
                    acc[r][q] += kk[r] * vv[q];
        }
    }

    // write final M tile
    #pragma unroll
    for (int r = 0; r < 8; r++) {
        *reinterpret_cast<float4*>(&out[(((size_t)bh * Dq) + d0 + r) * Dq + e0]) =
            make_float4(acc[r][0], acc[r][1], acc[r][2], acc[r][3]);
        *reinterpret_cast<float4*>(&out[(((size_t)bh * Dq) + d0 + r) * Dq + e0 + 4]) =
            make_float4(acc[r][4], acc[r][5], acc[r][6], acc[r][7]);
    }
}

// ---------------------------------------------------------------------------
extern "C" void kernel_launch(void* const* d_in, const int* in_sizes, int n_in,
                              void* d_out, int out_size)
{
    const float* x      = (const float*)d_in[0];
    const float* M      = (const float*)d_in[1];
    const float* router = (const float*)d_in[2];
    const int*   memid  = (const int*)d_in[3];
    const float* Wk     = (const float*)d_in[4];
    const float* bk     = (const float*)d_in[5];
    const float* Wv     = (const float*)d_in[6];
    const float* bv     = (const float*)d_in[7];
    const float* Wf     = (const float*)d_in[8];
    const float* bf     = (const float*)d_in[9];

    int nm = in_sizes[2] / (Bq * Sq);   // router last-dim (expected 4)

    scan_kernel<<<BH, 256>>>(x, router, memid, Wf, bf, nm);

    static bool attr_done = false;
    if (!attr_done) {
        cudaFuncSetAttribute(mem_kernel,
                             cudaFuncAttributeMaxDynamicSharedMemorySize,
                             SMEM_FLOATS * 4);
        attr_done = true;
    }
    mem_kernel<<<BH, 256, SMEM_FLOATS * 4>>>(x, M, Wk, bk, Wv, bv, (float*)d_out);
}

// round 4
// speedup vs baseline: 2.3752x; 2.3752x over previous
#include <cuda_runtime.h>

#define Bq 16
#define Sq 2048
#define Dq 128
#define Hq 8
#define BH (Bq*Hq)
#define CHUNK 32
#define CUT 1e-12f
#define SMEM_FLOATS 45600

// scratch (allocation-free rule: device globals)
__device__ float g_f[BH * Sq];
__device__ float g_c[BH * Sq];
__device__ float g_P[BH];
__device__ int   g_t0[BH];

// ---------------------------------------------------------------------------
// Kernel A1: f logits, massively parallel.
// grid = B * (Sq/32) = 1024 blocks, 128 threads. Block handles 32 timesteps
// for all 8 heads: load x tile (32x128) + Wf (128x8) to smem, each thread
// computes 2 of the 256 outputs. g_f[bh][t] = sigmoid(x_t . Wf[:,h] + bf[h]).
// ---------------------------------------------------------------------------
__global__ __launch_bounds__(128) void fproj_kernel(
    const float* __restrict__ x, const float* __restrict__ Wf,
    const float* __restrict__ bf, float* __restrict__ gf)
{
    __shared__ float xs[32 * 132];     // padded stride 132
    __shared__ float wfs[Dq * Hq];

    int tid = threadIdx.x;
    int blk = blockIdx.x;
    int b = blk >> 6;
    int tbase = (blk & 63) * 32;

    // Wf: 1024 floats
    for (int i = tid; i < Dq * Hq; i += 128) wfs[i] = Wf[i];

    // x tile: 1024 float4s
    #pragma unroll
    for (int j = 0; j < 8; j++) {
        int fid = tid + 128 * j;
        int t = fid >> 5, dq = fid & 31;
        float4 xv = *reinterpret_cast<const float4*>(
            &x[((size_t)b * Sq + tbase + t) * Dq + dq * 4]);
        xs[t * 132 + dq * 4 + 0] = xv.x;
        xs[t * 132 + dq * 4 + 1] = xv.y;
        xs[t * 132 + dq * 4 + 2] = xv.z;
        xs[t * 132 + dq * 4 + 3] = xv.w;
    }
    __syncthreads();

    #pragma unroll
    for (int j = 0; j < 2; j++) {
        int o = tid + 128 * j;
        int tl = o >> 3, h = o & 7;
        float acc = bf[h];
        #pragma unroll 8
        for (int d = 0; d < Dq; d++)
            acc += xs[tl * 132 + d] * wfs[d * Hq + h];
        gf[((size_t)(b * Hq + h)) * Sq + tbase + tl] =
            1.0f / (1.0f + __expf(-acc));
    }
}

// ---------------------------------------------------------------------------
// Kernel A2: per-(b,h) suffix-product scan over precomputed f.
// c_t = w_t * prod_{t'>t} f_{t'}; P = prod_t f_t; t0 = first t with sp>=CUT.
// ---------------------------------------------------------------------------
__global__ __launch_bounds__(256) void scan_kernel(
    const float* __restrict__ gf, const float* __restrict__ router,
    const int* __restrict__ memid, int nm)
{
    __shared__ float f_s[Sq];
    __shared__ float scanbuf[256];
    __shared__ int t0_sh;

    int tid = threadIdx.x;
    int bh = blockIdx.x;
    int b = bh >> 3;
    if (tid == 0) t0_sh = Sq;

    for (int i = tid; i < Sq; i += 256)
        f_s[i] = gf[(size_t)bh * Sq + i];
    __syncthreads();

    // per-thread chunk of 8 products
    float p = 1.0f;
    #pragma unroll
    for (int j = 0; j < 8; j++) p *= f_s[tid * 8 + j];
    scanbuf[tid] = p;
    __syncthreads();

    // inclusive suffix-product scan over the 256 chunk products
    for (int off = 1; off < 256; off <<= 1) {
        float v = (tid + off < 256) ? scanbuf[tid + off] : 1.0f;
        __syncthreads();
        scanbuf[tid] *= v;
        __syncthreads();
    }
    if (tid == 0) g_P[bh] = scanbuf[0];

    float running = (tid < 255) ? scanbuf[tid + 1] : 1.0f;  // suffix excl. my chunk
    int mid = *memid;
    int myt0 = Sq;
    #pragma unroll
    for (int j = 7; j >= 0; --j) {
        int t = tid * 8 + j;
        float sp = running;                       // prod_{t' > t} f
        float w = router[((size_t)b * Sq + t) * nm + mid];
        g_c[(size_t)bh * Sq + t] = w * sp;
        if (sp >= CUT) myt0 = t;                  // sp monotone nondecreasing in t
        running *= f_s[t];
    }
    if (myt0 < Sq) atomicMin(&t0_sh, myt0);
    __syncthreads();
    if (tid == 0) g_t0[bh] = t0_sh & ~(CHUNK - 1);   // chunk-aligned start
}

// ---------------------------------------------------------------------------
// Kernel B: per (b,h):
//   M_out = P*M0 + sum_{t>=t0} c_t * (x_t Wk_h + bk_h)(x_t Wv_h + bv_h)^T
// 512 threads (16 warps -> latency hiding); each thread owns a 4x8 tile of M.
// Per chunk: stage x^T -> project K/V (threads split in half) -> rank-32 update.
// ---------------------------------------------------------------------------
__global__ __launch_bounds__(512) void mem_kernel(
    const float* __restrict__ x, const float* __restrict__ M0,
    const float* __restrict__ Wk, const float* __restrict__ bk,
    const float* __restrict__ Wv, const float* __restrict__ bv,
    float* __restrict__ out)
{
    extern __shared__ float sm[];
    float* Wk_s = sm;                 // 128*128
    float* Wv_s = sm + 16384;         // 128*128
    float* xT   = sm + 32768;         // 128 rows * stride 36
    float* k_s  = sm + 37376;         // 32*128  (rows pre-scaled by c_t)
    float* v_s  = sm + 41472;         // 32*128
    float* c_s  = sm + 45568;         // 32

    int tid = threadIdx.x;
    int bh = blockIdx.x;
    int b = bh >> 3, h = bh & 7;

    // cache this head's Wk / Wv column blocks in smem
    for (int idx = tid; idx < Dq * 32; idx += 512) {
        int d = idx >> 5, q = idx & 31;
        *reinterpret_cast<float4*>(&Wk_s[d * Dq + q * 4]) =
            *reinterpret_cast<const float4*>(&Wk[(size_t)d * (Dq * Hq) + h * Dq + q * 4]);
        *reinterpret_cast<float4*>(&Wv_s[d * Dq + q * 4]) =
            *reinterpret_cast<const float4*>(&Wv[(size_t)d * (Dq * Hq) + h * Dq + q * 4]);
    }

    // M accumulator: thread owns rows d0..d0+3, cols e0..e0+7
    int dg = tid >> 4, eg = tid & 15;
    int d0 = dg * 4, e0 = eg * 8;
    float acc[4][8];
    float P = g_P[bh];
    #pragma unroll
    for (int r = 0; r < 4; r++) {
        float4 m0 = *reinterpret_cast<const float4*>(
            &M0[(((size_t)bh * Dq) + d0 + r) * Dq + e0]);
        float4 m1 = *reinterpret_cast<const float4*>(
            &M0[(((size_t)bh * Dq) + d0 + r) * Dq + e0 + 4]);
        acc[r][0] = P * m0.x; acc[r][1] = P * m0.y;
        acc[r][2] = P * m0.z; acc[r][3] = P * m0.w;
        acc[r][4] = P * m1.x; acc[r][5] = P * m1.y;
        acc[r][6] = P * m1.z; acc[r][7] = P * m1.w;
    }

    // projection mapping: lower 256 threads -> K, upper 256 -> V
    // each computes a 2-row x 8-col tile of the (32 x 128) chunk matrix
    int half = tid >> 8;
    int id2 = tid & 255;
    int rg = id2 & 15;       // rows rg*2 .. rg*2+1
    int cg = id2 >> 4;       // cols cg*8 .. cg*8+7
    const float* Ws = half ? Wv_s : Wk_s;
    float* op = half ? v_s : k_s;
    float bias[8];
    {
        const float* bsrc = half ? bv : bk;
        #pragma unroll
        for (int j = 0; j < 8; j++) bias[j] = bsrc[h * Dq + cg * 8 + j];
    }

    int t0 = g_t0[bh];
    for (int tc = t0; tc < Sq; tc += CHUNK) {
        __syncthreads();
        // stage x chunk transposed: xT[d][i] = x[b, tc+i, d]
        {
            int i = tid & 31, ds = (tid >> 5) << 3;
            int t = tc + i;
            #pragma unroll
            for (int q = 0; q < 2; q++) {
                float4 xv = *reinterpret_cast<const float4*>(
                    &x[((size_t)b * Sq + t) * Dq + ds + q * 4]);
                xT[(ds + q * 4 + 0) * 36 + i] = xv.x;
                xT[(ds + q * 4 + 1) * 36 + i] = xv.y;
                xT[(ds + q * 4 + 2) * 36 + i] = xv.z;
                xT[(ds + q * 4 + 3) * 36 + i] = xv.w;
            }
            if (tid < CHUNK)
                c_s[tid] = g_c[(size_t)bh * Sq + tc + tid];
        }
        __syncthreads();

        // projection: this thread's K-or-V chunk tile (2x8)
        float pa[2][8];
        #pragma unroll
        for (int r = 0; r < 2; r++)
            #pragma unroll
            for (int j = 0; j < 8; j++) pa[r][j] = 0.f;

        #pragma unroll 4
        for (int d = 0; d < Dq; d++) {
            float2 xa = *reinterpret_cast<const float2*>(&xT[d * 36 + rg * 2]);
            float4 w0 = *reinterpret_cast<const float4*>(&Ws[d * Dq + cg * 8]);
            float4 w1 = *reinterpret_cast<const float4*>(&Ws[d * Dq + cg * 8 + 4]);
            float xr[2] = {xa.x, xa.y};
            float wv[8] = {w0.x, w0.y, w0.z, w0.w, w1.x, w1.y, w1.z, w1.w};
            #pragma unroll
            for (int r = 0; r < 2; r++)
                #pragma unroll
                for (int j = 0; j < 8; j++)
                    pa[r][j] += xr[r] * wv[j];
        }
        #pragma unroll
        for (int r = 0; r < 2; r++) {
            int row = rg * 2 + r;
            float scale = half ? 1.0f : c_s[row];   // fold c_t into k rows
            float o[8];
            #pragma unroll
            for (int j = 0; j < 8; j++) o[j] = (pa[r][j] + bias[j]) * scale;
            *reinterpret_cast<float4*>(&op[row * Dq + cg * 8]) =
                make_float4(o[0], o[1], o[2], o[3]);
            *reinterpret_cast<float4*>(&op[row * Dq + cg * 8 + 4]) =
                make_float4(o[4], o[5], o[6], o[7]);
        }
        __syncthreads();

        // rank-32 outer-product update of the 4x8 tile
        #pragma unroll 4
        for (int i = 0; i < CHUNK; i++) {
            float4 k0 = *reinterpret_cast<const float4*>(&k_s[i * Dq + d0]);
            float4 v0 = *reinterpret_cast<const float4*>(&v_s[i * Dq + e0]);
            float4 v1 = *reinterpret_cast<const float4*>(&v_s[i * Dq + e0 + 4]);
            float kk[4] = {k0.x, k0.y, k0.z, k0.w};
            float vv[8] = {v0.x, v0.y, v0.z, v0.w, v1.x, v1.y, v1.z, v1.w};
            #pragma unroll
            for (int r = 0; r < 4; r++)
                #pragma unroll
                for (int q = 0; q < 8; q++)
                    acc[r][q] += kk[r] * vv[q];
        }
    }

    // write final M tile
    #pragma unroll
    for (int r = 0; r < 4; r++) {
        *reinterpret_cast<float4*>(&out[(((size_t)bh * Dq) + d0 + r) * Dq + e0]) =
            make_float4(acc[r][0], acc[r][1], acc[r][2], acc[r][3]);
        *reinterpret_cast<float4*>(&out[(((size_t)bh * Dq) + d0 + r) * Dq + e0 + 4]) =
            make_float4(acc[r][4], acc[r][5], acc[r][6], acc[r][7]);
    }
}

// ---------------------------------------------------------------------------
extern "C" void kernel_launch(void* const* d_in, const int* in_sizes, int n_in,
                              void* d_out, int out_size)
{
    const float* x      = (const float*)d_in[0];
    const float* M      = (const float*)d_in[1];
    const float* router = (const float*)d_in[2];
    const int*   memid  = (const int*)d_in[3];
    const float* Wk     = (const float*)d_in[4];
    const float* bk     = (const float*)d_in[5];
    const float* Wv     = (const float*)d_in[6];
    const float* bv     = (const float*)d_in[7];
    const float* Wf     = (const float*)d_in[8];
    const float* bf     = (const float*)d_in[9];

    int nm = in_sizes[2] / (Bq * Sq);   // router last-dim (expected 4)

    float* gf;
    cudaGetSymbolAddress((void**)&gf, g_f);

    fproj_kernel<<<Bq * (Sq / 32), 128>>>(x, Wf, bf, gf);
    scan_kernel<<<BH, 256>>>(gf, router, memid, nm);

    static bool attr_done = false;
    if (!attr_done) {
        cudaFuncSetAttribute(mem_kernel,
                             cudaFuncAttributeMaxDynamicSharedMemorySize,
                             SMEM_FLOATS * 4);
        attr_done = true;
    }
    mem_kernel<<<BH, 512, SMEM_FLOATS * 4>>>(x, M, Wk, bk, Wv, bv, (float*)d_out);
}

// round 5
// speedup vs baseline: 2.9722x; 1.2513x over previous
#include <cuda_runtime.h>
#include <math.h>

#define Bq 16
#define Sq 2048
#define Dq 128
#define Hq 8
#define BH 128
#define MCH 32                 // mem chunk (timesteps per work item)
#define SCH 64                 // scan chunk
#define NCH (Sq/SCH)
#define CUT 1e-7f
#define MAXITEMS (BH*(Sq/MCH))
#define MEM_SMEM_FLOATS 45600

// device scratch (allocation-free rule)
__device__ float g_c[BH * Sq];
__device__ int   g_items[MAXITEMS];
__device__ int   g_nitems;
__device__ int   g_fetch;

__global__ void zero_kernel() { g_nitems = 0; g_fetch = 0; }

// ---------------------------------------------------------------------------
// Backward scan, one block per (b,h): computes f_t = sigmoid(x_t.Wf_h + bf_h)
// on the fly, walking chunks of 64 timesteps from the end. Maintains suffix
// product sp; writes c_t = w_t * sp_t; early-exits when sp < CUT. Emits
// (bh, chunk) work items for the active tail and initializes out = P*M0.
// ---------------------------------------------------------------------------
__global__ __launch_bounds__(256) void scan_kernel(
    const float* __restrict__ x, const float* __restrict__ router,
    const int* __restrict__ memid, const float* __restrict__ Wf,
    const float* __restrict__ bf, const float* __restrict__ M0,
    float* __restrict__ out, int nm)
{
    __shared__ float xT[Dq * 68];   // [d][t], stride 68
    __shared__ float wfh[Dq];
    __shared__ float f_s[SCH];
    __shared__ float csp[SCH];
    __shared__ float s_sp, s_newsp;
    __shared__ int   s_t0i;

    int tid = threadIdx.x, bh = blockIdx.x, b = bh >> 3, h = bh & 7;
    for (int d = tid; d < Dq; d += 256) wfh[d] = Wf[d * Hq + h];
    float bfh = bf[h];
    int mid = *memid;
    if (tid == 0) s_sp = 1.0f;
    __syncthreads();

    int t0_exact = 0;
    float P = 0.0f;

    for (int ci = NCH - 1; ci >= 0; ci--) {
        int tc = ci * SCH;
        // stage x[tc..tc+64) transposed into smem (coalesced loads)
        for (int q = tid; q < SCH * Dq / 4; q += 256) {
            int t = q >> 5, dq = q & 31;
            float4 xv = *(const float4*)&x[((size_t)b * Sq + tc + t) * Dq + dq * 4];
            xT[(dq * 4 + 0) * 68 + t] = xv.x;
            xT[(dq * 4 + 1) * 68 + t] = xv.y;
            xT[(dq * 4 + 2) * 68 + t] = xv.z;
            xT[(dq * 4 + 3) * 68 + t] = xv.w;
        }
        __syncthreads();
        if (tid < SCH) {
            float acc = bfh;
            #pragma unroll 8
            for (int d = 0; d < Dq; d++) acc += xT[d * 68 + tid] * wfh[d];
            f_s[tid] = 1.0f / (1.0f + expf(-acc));
        }
        __syncthreads();
        if (tid == 0) {
            float run = s_sp;           // prod of all f after this chunk
            int t0i = SCH - 1;
            for (int i = SCH - 1; i >= 0; i--) {
                csp[i] = run;           // prod_{t'>tc+i} f
                if (run >= CUT) t0i = i;
                run *= f_s[i];
            }
            s_newsp = run;
            s_t0i = t0i;
        }
        __syncthreads();
        if (tid < SCH) {
            float w = router[((size_t)b * Sq + tc + tid) * nm + mid];
            g_c[(size_t)bh * Sq + tc + tid] = w * csp[tid];
        }
        float nsp = s_newsp;
        if (nsp < CUT) { t0_exact = tc + s_t0i; break; }   // uniform decision
        if (tid == 0) s_sp = nsp;
        __syncthreads();
        if (ci == 0) { P = nsp; t0_exact = 0; }
    }

    // emit work items for active tail (chunk-aligned)
    int t0 = t0_exact & ~(MCH - 1);
    if (tid == 0) {
        int cnt = (Sq - t0) / MCH;
        int base = atomicAdd(&g_nitems, cnt);
        for (int j = 0; j < cnt; j++)
            g_items[base + j] = (bh << 8) | (t0 / MCH + j);
    }

    // initialize out = P * M0 for this bh (P=0 if early-exited: negligible)
    size_t obase = (size_t)bh * Dq * Dq;
    for (int q = tid; q < Dq * Dq / 4; q += 256) {
        float4 m = *(const float4*)&M0[obase + q * 4];
        m.x *= P; m.y *= P; m.z *= P; m.w *= P;
        *(float4*)&out[obase + q * 4] = m;
    }
}

// ---------------------------------------------------------------------------
// Persistent work-queue kernel. Item = (bh, chunk of 32 timesteps):
//   out[bh] += sum_t c_t * (x_t Wk_h + bk_h)(x_t Wv_h + bv_h)^T   (atomicAdd)
// 512 threads: lower half projects K (rows scaled by c), upper half V;
// then each thread does a 4x8 outer-product tile and atomically accumulates.
// ---------------------------------------------------------------------------
__global__ __launch_bounds__(512) void mem_kernel(
    const float* __restrict__ x,
    const float* __restrict__ Wk, const float* __restrict__ bk,
    const float* __restrict__ Wv, const float* __restrict__ bv,
    float* __restrict__ out)
{
    extern __shared__ float sm[];
    float* Wk_s = sm;                 // 128*128
    float* Wv_s = sm + 16384;         // 128*128
    float* xT   = sm + 32768;         // 128 * stride 36
    float* k_s  = sm + 37376;         // 32*128 (c-scaled)
    float* v_s  = sm + 41472;         // 32*128
    float* c_s  = sm + 45568;         // 32

    __shared__ int s_it;
    int tid = threadIdx.x;
    int nitems = g_nitems;

    int dg = tid >> 4, eg = tid & 15, d0 = dg * 4, e0 = eg * 8;
    int half = tid >> 8, id2 = tid & 255, rg = id2 & 15, cg = id2 >> 4;
    float* op = half ? v_s : k_s;
    const float* Ws = half ? Wv_s : Wk_s;
    const float* bsrc = half ? bv : bk;

    int prev_h = -1;

    while (1) {
        if (tid == 0) s_it = atomicAdd(&g_fetch, 1);
        __syncthreads();
        int it = s_it;
        if (it >= nitems) break;
        int item = g_items[it];
        int bh = item >> 8, ck = item & 255;
        int b = bh >> 3, h = bh & 7, tc = ck * MCH;

        if (h != prev_h) {                       // uniform across block
            for (int idx = tid; idx < Dq * 32; idx += 512) {
                int d = idx >> 5, q = idx & 31;
                *(float4*)&Wk_s[d * Dq + q * 4] =
                    *(const float4*)&Wk[(size_t)d * (Dq * Hq) + h * Dq + q * 4];
                *(float4*)&Wv_s[d * Dq + q * 4] =
                    *(const float4*)&Wv[(size_t)d * (Dq * Hq) + h * Dq + q * 4];
            }
            prev_h = h;
        }

        float bias[8];
        #pragma unroll
        for (int j = 0; j < 8; j++) bias[j] = bsrc[h * Dq + cg * 8 + j];

        // stage x chunk transposed + c
        {
            int i = tid & 31, ds = (tid >> 5) << 3;
            #pragma unroll
            for (int q = 0; q < 2; q++) {
                float4 xv = *(const float4*)&x[((size_t)b * Sq + tc + i) * Dq + ds + q * 4];
                xT[(ds + q * 4 + 0) * 36 + i] = xv.x;
                xT[(ds + q * 4 + 1) * 36 + i] = xv.y;
                xT[(ds + q * 4 + 2) * 36 + i] = xv.z;
                xT[(ds + q * 4 + 3) * 36 + i] = xv.w;
            }
            if (tid < MCH) c_s[tid] = g_c[(size_t)bh * Sq + tc + tid];
        }
        __syncthreads();

        // projection: 2x8 tile of the 32x128 K-or-V chunk
        float pa[2][8];
        #pragma unroll
        for (int r = 0; r < 2; r++)
            #pragma unroll
            for (int j = 0; j < 8; j++) pa[r][j] = 0.f;

        #pragma unroll 4
        for (int d = 0; d < Dq; d++) {
            float2 xa = *(const float2*)&xT[d * 36 + rg * 2];
            float4 w0 = *(const float4*)&Ws[d * Dq + cg * 8];
            float4 w1 = *(const float4*)&Ws[d * Dq + cg * 8 + 4];
            float xr[2] = {xa.x, xa.y};
            float wv[8] = {w0.x, w0.y, w0.z, w0.w, w1.x, w1.y, w1.z, w1.w};
            #pragma unroll
            for (int r = 0; r < 2; r++)
                #pragma unroll
                for (int j = 0; j < 8; j++)
                    pa[r][j] += xr[r] * wv[j];
        }
        #pragma unroll
        for (int r = 0; r < 2; r++) {
            int row = rg * 2 + r;
            float scale = half ? 1.0f : c_s[row];
            float o[8];
            #pragma unroll
            for (int j = 0; j < 8; j++) o[j] = (pa[r][j] + bias[j]) * scale;
            *(float4*)&op[row * Dq + cg * 8]     = make_float4(o[0], o[1], o[2], o[3]);
            *(float4*)&op[row * Dq + cg * 8 + 4] = make_float4(o[4], o[5], o[6], o[7]);
        }
        __syncthreads();

        // rank-32 outer-product into local 4x8 tile
        float acc[4][8];
        #pragma unroll
        for (int r = 0; r < 4; r++)
            #pragma unroll
            for (int j = 0; j < 8; j++) acc[r][j] = 0.f;

        #pragma unroll 4
        for (int i = 0; i < MCH; i++) {
            float4 k0 = *(const float4*)&k_s[i * Dq + d0];
            float4 v0 = *(const float4*)&v_s[i * Dq + e0];
            float4 v1 = *(const float4*)&v_s[i * Dq + e0 + 4];
            float kk[4] = {k0.x, k0.y, k0.z, k0.w};
            float vv[8] = {v0.x, v0.y, v0.z, v0.w, v1.x, v1.y, v1.z, v1.w};
            #pragma unroll
            for (int r = 0; r < 4; r++)
                #pragma unroll
                for (int q = 0; q < 8; q++)
                    acc[r][q] += kk[r] * vv[q];
        }

        size_t ob = ((size_t)bh * Dq + d0) * Dq + e0;
        #pragma unroll
        for (int r = 0; r < 4; r++)
            #pragma unroll
            for (int j = 0; j < 8; j++)
                atomicAdd(&out[ob + (size_t)r * Dq + j], acc[r][j]);

        __syncthreads();   // protect smem + s_it before next item
    }
}

// ---------------------------------------------------------------------------
extern "C" void kernel_launch(void* const* d_in, const int* in_sizes, int n_in,
                              void* d_out, int out_size)
{
    const float* x      = (const float*)d_in[0];
    const float* M      = (const float*)d_in[1];
    const float* router = (const float*)d_in[2];
    const int*   memid  = (const int*)d_in[3];
    const float* Wk     = (const float*)d_in[4];
    const float* bk     = (const float*)d_in[5];
    const float* Wv     = (const float*)d_in[6];
    const float* bv     = (const float*)d_in[7];
    const float* Wf     = (const float*)d_in[8];
    const float* bf     = (const float*)d_in[9];

    int nm = in_sizes[2] / (Bq * Sq);   // router last-dim (4)

    zero_kernel<<<1, 1>>>();
    scan_kernel<<<BH, 256>>>(x, router, memid, Wf, bf, M, (float*)d_out, nm);

    static bool attr_done = false;
    if (!attr_done) {
        cudaFuncSetAttribute(mem_kernel,
                             cudaFuncAttributeMaxDynamicSharedMemorySize,
                             MEM_SMEM_FLOATS * 4);
        attr_done = true;
    }
    mem_kernel<<<160, 512, MEM_SMEM_FLOATS * 4>>>(x, Wk, bk, Wv, bv, (float*)d_out);
}

// round 6
// speedup vs baseline: 4.5353x; 1.5259x over previous
#include <cuda_runtime.h>
#include <math.h>

#define Bq 16
#define Sq 2048
#define Dq 128
#define Hq 8
#define BH 128
#define MCH 32                 // mem chunk
#define SCH 64                 // scan chunk
#define NCH (Sq/SCH)
#define CUT 1e-7f

// dynamic smem float layout
#define OFF_WK  0
#define OFF_WV  16384
#define OFF_BUF 32768          // scan xT (128*68=8704) OR mem xT(4608)+k_s(4096)+v_s(4096)
#define OFF_C   45568          // c[2048]
#define SMEM_FLOATS 47616

// ---------------------------------------------------------------------------
// One block per (b,h). Phases:
//  1) backward scan w/ early exit: f_t = sigmoid(x_t.Wf_h+bf_h) on the fly,
//     suffix products -> c_t = w_t * sp_t in SMEM; stop when sp < CUT.
//  2) acc = P*M0 (registers), then chunked K/V projection + rank-32 outer
//     products accumulating in the same registers; single store to out.
// ---------------------------------------------------------------------------
__global__ __launch_bounds__(512) void fused_kernel(
    const float* __restrict__ x, const float* __restrict__ M0,
    const float* __restrict__ router, const int* __restrict__ memid,
    const float* __restrict__ Wk, const float* __restrict__ bk,
    const float* __restrict__ Wv, const float* __restrict__ bv,
    const float* __restrict__ Wf, const float* __restrict__ bf,
    float* __restrict__ out, int nm)
{
    extern __shared__ float sm[];
    float* Wk_s = sm + OFF_WK;
    float* Wv_s = sm + OFF_WV;
    float* bufA = sm + OFF_BUF;            // scan xT, stride 68
    float* xT   = sm + OFF_BUF;            // mem xT, stride 36
    float* k_s  = sm + OFF_BUF + 4608;
    float* v_s  = sm + OFF_BUF + 8704;
    float* c_s  = sm + OFF_C;              // indexed by global t

    __shared__ float wfh[Dq];
    __shared__ float f_s[SCH], csp[SCH];
    __shared__ float s_sp, s_newsp;
    __shared__ int   s_t0i;

    int tid = threadIdx.x, bh = blockIdx.x, b = bh >> 3, h = bh & 7;

    // head weights into smem (used in phase 2; issue loads early)
    for (int idx = tid; idx < Dq * 32; idx += 512) {
        int d = idx >> 5, q = idx & 31;
        *(float4*)&Wk_s[d * Dq + q * 4] =
            *(const float4*)&Wk[(size_t)d * (Dq * Hq) + h * Dq + q * 4];
        *(float4*)&Wv_s[d * Dq + q * 4] =
            *(const float4*)&Wv[(size_t)d * (Dq * Hq) + h * Dq + q * 4];
    }
    for (int d = tid; d < Dq; d += 512) wfh[d] = Wf[d * Hq + h];
    float bfh = bf[h];
    int mid = *memid;
    if (tid == 0) s_sp = 1.0f;
    __syncthreads();

    // ---- phase 1: backward scan with early exit ----
    int t0_exact = 0;
    float P = 0.0f;

    for (int ci = NCH - 1; ci >= 0; ci--) {
        int tc = ci * SCH;
        // stage x[tc..tc+64) transposed (stride 68)
        for (int q = tid; q < SCH * Dq / 4; q += 512) {
            int t = q >> 5, dq = q & 31;
            float4 xv = *(const float4*)&x[((size_t)b * Sq + tc + t) * Dq + dq * 4];
            bufA[(dq * 4 + 0) * 68 + t] = xv.x;
            bufA[(dq * 4 + 1) * 68 + t] = xv.y;
            bufA[(dq * 4 + 2) * 68 + t] = xv.z;
            bufA[(dq * 4 + 3) * 68 + t] = xv.w;
        }
        __syncthreads();
        // f for 64 timesteps: 8 threads per t, shfl-reduce
        {
            int t = tid >> 3, sub = tid & 7;
            float a = 0.f;
            #pragma unroll
            for (int j = 0; j < 16; j++) {
                int d = sub * 16 + j;
                a += bufA[d * 68 + t] * wfh[d];
            }
            a += __shfl_xor_sync(0xffffffffu, a, 1);
            a += __shfl_xor_sync(0xffffffffu, a, 2);
            a += __shfl_xor_sync(0xffffffffu, a, 4);
            if (sub == 0) f_s[t] = 1.0f / (1.0f + __expf(-(a + bfh)));
        }
        __syncthreads();
        if (tid == 0) {
            float run = s_sp;              // prod of all f after this chunk
            int t0i = SCH - 1;
            for (int i = SCH - 1; i >= 0; i--) {
                csp[i] = run;              // prod_{t' > tc+i} f
                if (run >= CUT) t0i = i;
                run *= f_s[i];
            }
            s_newsp = run;
            s_t0i = t0i;
        }
        __syncthreads();
        if (tid < SCH) {
            float w = router[((size_t)b * Sq + tc + tid) * nm + mid];
            c_s[tc + tid] = w * csp[tid];
        }
        float nsp = s_newsp;
        if (nsp < CUT) { t0_exact = tc + s_t0i; break; }   // uniform decision
        if (tid == 0) s_sp = nsp;
        __syncthreads();
        if (ci == 0) { P = nsp; t0_exact = 0; }
    }
    __syncthreads();   // c_s complete; bufA region free for reuse

    // ---- phase 2: acc = P*M0, then chunked projection + outer products ----
    int dg = tid >> 4, eg = tid & 15, d0 = dg * 4, e0 = eg * 8;
    float acc[4][8];
    #pragma unroll
    for (int r = 0; r < 4; r++) {
        float4 m0 = *(const float4*)&M0[(((size_t)bh * Dq) + d0 + r) * Dq + e0];
        float4 m1 = *(const float4*)&M0[(((size_t)bh * Dq) + d0 + r) * Dq + e0 + 4];
        acc[r][0] = P * m0.x; acc[r][1] = P * m0.y;
        acc[r][2] = P * m0.z; acc[r][3] = P * m0.w;
        acc[r][4] = P * m1.x; acc[r][5] = P * m1.y;
        acc[r][6] = P * m1.z; acc[r][7] = P * m1.w;
    }

    int half = tid >> 8, id2 = tid & 255, rg = id2 & 15, cg = id2 >> 4;
    float* op = half ? v_s : k_s;
    const float* Ws = half ? Wv_s : Wk_s;
    float bias[8];
    {
        const float* bsrc = half ? bv : bk;
        #pragma unroll
        for (int j = 0; j < 8; j++) bias[j] = bsrc[h * Dq + cg * 8 + j];
    }

    int t0 = t0_exact & ~(MCH - 1);
    for (int tc = t0; tc < Sq; tc += MCH) {
        __syncthreads();
        // stage x chunk transposed (stride 36)
        {
            int i = tid & 31, ds = (tid >> 5) << 3;
            #pragma unroll
            for (int q = 0; q < 2; q++) {
                float4 xv = *(const float4*)&x[((size_t)b * Sq + tc + i) * Dq + ds + q * 4];
                xT[(ds + q * 4 + 0) * 36 + i] = xv.x;
                xT[(ds + q * 4 + 1) * 36 + i] = xv.y;
                xT[(ds + q * 4 + 2) * 36 + i] = xv.z;
                xT[(ds + q * 4 + 3) * 36 + i] = xv.w;
            }
        }
        __syncthreads();

        // projection: 2x8 tile of the 32x128 K-or-V chunk
        float pa[2][8];
        #pragma unroll
        for (int r = 0; r < 2; r++)
            #pragma unroll
            for (int j = 0; j < 8; j++) pa[r][j] = 0.f;

        #pragma unroll 4
        for (int d = 0; d < Dq; d++) {
            float2 xa = *(const float2*)&xT[d * 36 + rg * 2];
            float4 w0 = *(const float4*)&Ws[d * Dq + cg * 8];
            float4 w1 = *(const float4*)&Ws[d * Dq + cg * 8 + 4];
            float xr[2] = {xa.x, xa.y};
            float wv[8] = {w0.x, w0.y, w0.z, w0.w, w1.x, w1.y, w1.z, w1.w};
            #pragma unroll
            for (int r = 0; r < 2; r++)
                #pragma unroll
                for (int j = 0; j < 8; j++)
                    pa[r][j] += xr[r] * wv[j];
        }
        #pragma unroll
        for (int r = 0; r < 2; r++) {
            int row = rg * 2 + r;
            float scale = half ? 1.0f : c_s[tc + row];   // fold c_t into k rows
            float o[8];
            #pragma unroll
            for (int j = 0; j < 8; j++) o[j] = (pa[r][j] + bias[j]) * scale;
            *(float4*)&op[row * Dq + cg * 8]     = make_float4(o[0], o[1], o[2], o[3]);
            *(float4*)&op[row * Dq + cg * 8 + 4] = make_float4(o[4], o[5], o[6], o[7]);
        }
        __syncthreads();

        // rank-32 outer-product update of the 4x8 tile
        #pragma unroll 4
        for (int i = 0; i < MCH; i++) {
            float4 k0 = *(const float4*)&k_s[i * Dq + d0];
            float4 v0 = *(const float4*)&v_s[i * Dq + e0];
            float4 v1 = *(const float4*)&v_s[i * Dq + e0 + 4];
            float kk[4] = {k0.x, k0.y, k0.z, k0.w};
            float vv[8] = {v0.x, v0.y, v0.z, v0.w, v1.x, v1.y, v1.z, v1.w};
            #pragma unroll
            for (int r = 0; r < 4; r++)
                #pragma unroll
                for (int q = 0; q < 8; q++)
                    acc[r][q] += kk[r] * vv[q];
        }
    }

    // single store of the final tile
    #pragma unroll
    for (int r = 0; r < 4; r++) {
        *(float4*)&out[(((size_t)bh * Dq) + d0 + r) * Dq + e0] =
            make_float4(acc[r][0], acc[r][1], acc[r][2], acc[r][3]);
        *(float4*)&out[(((size_t)bh * Dq) + d0 + r) * Dq + e0 + 4] =
            make_float4(acc[r][4], acc[r][5], acc[r][6], acc[r][7]);
    }
}

// ---------------------------------------------------------------------------
extern "C" void kernel_launch(void* const* d_in, const int* in_sizes, int n_in,
                              void* d_out, int out_size)
{
    const float* x      = (const float*)d_in[0];
    const float* M      = (const float*)d_in[1];
    const float* router = (const float*)d_in[2];
    const int*   memid  = (const int*)d_in[3];
    const float* Wk     = (const float*)d_in[4];
    const float* bk     = (const float*)d_in[5];
    const float* Wv     = (const float*)d_in[6];
    const float* bv     = (const float*)d_in[7];
    const float* Wf     = (const float*)d_in[8];
    const float* bf     = (const float*)d_in[9];

    int nm = in_sizes[2] / (Bq * Sq);   // router last-dim (4)

    static bool attr_done = false;
    if (!attr_done) {
        cudaFuncSetAttribute(fused_kernel,
                             cudaFuncAttributeMaxDynamicSharedMemorySize,
                             SMEM_FLOATS * 4);
        attr_done = true;
    }
    fused_kernel<<<BH, 512, SMEM_FLOATS * 4>>>(
        x, M, router, memid, Wk, bk, Wv, bv, Wf, bf, (float*)d_out, nm);
}